// round 13
// baseline (speedup 1.0000x reference)
#include <cuda_runtime.h>
#include <cuda_fp16.h>
#include <cstdint>

// ---------------- problem constants ----------------
#define T_DIM   2048
#define B_DIM   16
#define H_DIM   1024
#define M_TOTAL (T_DIM * B_DIM)     // 32768 rows
#define W_ATT   3

// ---------------- GEMM tiling ----------------
#define TILE_M   64
#define TILE_N   256
#define KC       64                  // k elems per chunk
#define NCHUNKS  (H_DIM / KC)        // 16
#define NTILES   (H_DIM / TILE_N)    // 4
#define MTILES   (M_TOTAL / TILE_M)  // 512
#define GEMM_THREADS 512

// SMEM row stride: 64 fp16 = 128B data, padded to 144B (conflict-free ldmatrix)
#define ROWB     144
#define A_BYTES  (TILE_M * ROWB)     // 9216
#define B_BYTES  (TILE_N * ROWB)     // 36864
#define A_OFF    0
#define B_OFF    A_BYTES
#define STAGE_BYTES (A_BYTES + B_BYTES)   // 46080
#define PROJ_OFF (2 * STAGE_BYTES)        // 92160 (256 floats)
#define RED_OFF  (PROJ_OFF + 1024)        // 93184 (256 floats)
#define SMEM_TOTAL_GEMM (RED_OFF + 1024)  // 94208  (x2 CTAs = 188416 < 227KB)

// ---------------- global scratch ----------------
__device__ __half g_xh[(size_t)M_TOTAL * H_DIM];
__device__ __half g_whT[(size_t)H_DIM * H_DIM];   // [n][k]
__device__ float g_part[NTILES * M_TOTAL];

// ---------------- helpers ----------------
__device__ __forceinline__ uint32_t smem_u32(const void* p) {
    uint32_t a;
    asm("{ .reg .u64 t; cvta.to.shared.u64 t, %1; cvt.u32.u64 %0, t; }" : "=r"(a) : "l"(p));
    return a;
}

__device__ __forceinline__ void cp16(uint32_t dst, const void* src) {
    asm volatile("cp.async.cg.shared.global [%0], [%1], 16;\n"
                 :: "r"(dst), "l"(__cvta_generic_to_global(src)) : "memory");
}
#define CP_COMMIT() asm volatile("cp.async.commit_group;" ::: "memory")
#define CP_WAIT0()  asm volatile("cp.async.wait_group 0;"  ::: "memory")
#define CP_WAIT1()  asm volatile("cp.async.wait_group 1;"  ::: "memory")

__device__ __forceinline__ void ldsm_x4(uint32_t* r, uint32_t addr) {
    asm volatile("ldmatrix.sync.aligned.m8n8.x4.shared.b16 {%0,%1,%2,%3}, [%4];"
                 : "=r"(r[0]), "=r"(r[1]), "=r"(r[2]), "=r"(r[3]) : "r"(addr));
}

#define MMA_F16(c, a, b0v, b1v)                                               \
    asm volatile(                                                             \
        "mma.sync.aligned.m16n8k16.row.col.f32.f16.f16.f32 "                  \
        "{%0,%1,%2,%3}, {%4,%5,%6,%7}, {%8,%9}, {%0,%1,%2,%3};\n"             \
        : "+f"((c)[0]), "+f"((c)[1]), "+f"((c)[2]), "+f"((c)[3])              \
        : "r"((a)[0]), "r"((a)[1]), "r"((a)[2]), "r"((a)[3]),                 \
          "r"(b0v), "r"(b1v))

// ---------------- convert kernels ----------------
__global__ __launch_bounds__(256)
void convert_x_kernel(const float* __restrict__ X)
{
    size_t i = (size_t)blockIdx.x * 256 + threadIdx.x;    // float4 index
    float4 v = ((const float4*)X)[i];
    __half2 h0 = __float22half2_rn(make_float2(v.x, v.y));
    __half2 h1 = __float22half2_rn(make_float2(v.z, v.w));
    uint2 u;
    u.x = *(uint32_t*)&h0; u.y = *(uint32_t*)&h1;
    ((uint2*)g_xh)[i] = u;
}

__global__ __launch_bounds__(1024)
void convert_w_kernel(const float* __restrict__ W)
{
    __shared__ float t[32][33];
    int x = blockIdx.x * 32 + threadIdx.x;   // n
    int y = blockIdx.y * 32 + threadIdx.y;   // k
    t[threadIdx.y][threadIdx.x] = W[(size_t)y * H_DIM + x];
    __syncthreads();
    int n  = blockIdx.x * 32 + threadIdx.y;
    int kk = blockIdx.y * 32 + threadIdx.x;
    g_whT[(size_t)n * H_DIM + kk] = __float2half_rn(t[threadIdx.x][threadIdx.y]);
}

// ---------------- GEMM + fused tanh/proj epilogue ----------------
__device__ __forceinline__ void load_stage(uint32_t sbStage, int rowBase, int n0,
                                           int k0, int tid)
{
    // A: 64 rows x 8 x 16B  (512 copies, 1 per thread)
    {
        int row = tid >> 3, q = tid & 7;
        size_t off = (size_t)(rowBase + row) * H_DIM + k0 + q * 8;
        cp16(sbStage + A_OFF + row * ROWB + q * 16, g_xh + off);
    }
    // B: 256 rows x 8 x 16B (2048 copies, 4 per thread)
#pragma unroll
    for (int i = 0; i < 4; ++i) {
        int c = tid + i * 512;
        int row = c >> 3, q = c & 7;
        size_t off = (size_t)(n0 + row) * H_DIM + k0 + q * 8;
        cp16(sbStage + B_OFF + row * ROWB + q * 16, g_whT + off);
    }
}

__global__ __launch_bounds__(GEMM_THREADS, 2)
void gemm_scores_kernel(const float* __restrict__ proj)
{
    extern __shared__ __align__(16) char smem_raw[];
    const uint32_t sb = smem_u32(smem_raw);
    const int tid  = threadIdx.x;
    const int lane = tid & 31;
    const int wid  = tid >> 5;
    const int g    = lane >> 2;
    const int tg   = lane & 3;
    const int wm   = wid & 3;     // warp M (0..3): rows wm*16..+16
    const int wn   = wid >> 2;    // warp N (0..3): cols wn*64..+64

    const int mt = blockIdx.x >> 2;
    const int nt = blockIdx.x & 3;
    const int rowBase = mt * TILE_M;
    const int n0 = nt * TILE_N;

    float* projs = (float*)(smem_raw + PROJ_OFF);
    float* red   = (float*)(smem_raw + RED_OFF);
    if (tid < 256) projs[tid] = proj[n0 + tid];

    float C[8][4];
#pragma unroll
    for (int in_ = 0; in_ < 8; ++in_)
#pragma unroll
        for (int e = 0; e < 4; ++e) C[in_][e] = 0.0f;

    // per-lane ldmatrix base addresses (within a stage)
    const uint32_t aBaseRel = (uint32_t)(A_OFF +
        (wm * 16 + (lane & 15)) * ROWB + (lane >> 4) * 16);
    const uint32_t bBaseRel = (uint32_t)(B_OFF +
        (wn * 64 + (lane & 7) + ((lane >> 4) & 1) * 8) * ROWB + ((lane >> 3) & 1) * 16);

    load_stage(sb, rowBase, n0, 0, tid);
    CP_COMMIT();
    load_stage(sb + STAGE_BYTES, rowBase, n0, KC, tid);
    CP_COMMIT();

#pragma unroll 1
    for (int k = 0; k < NCHUNKS; ++k) {
        if (k < NCHUNKS - 1) { CP_WAIT1(); } else { CP_WAIT0(); }
        __syncthreads();

        const uint32_t sBase = sb + (uint32_t)(k & 1) * STAGE_BYTES;
        const uint32_t aB = sBase + aBaseRel;
        const uint32_t bB = sBase + bBaseRel;

#pragma unroll
        for (int ks = 0; ks < 4; ++ks) {
            uint32_t ah[4];
            ldsm_x4(ah, aB + ks * 32);
#pragma unroll
            for (int p = 0; p < 4; ++p) {
                uint32_t bh[4];
                ldsm_x4(bh, bB + p * (16 * ROWB) + ks * 32);
                MMA_F16(C[2 * p],     ah, bh[0], bh[1]);
                MMA_F16(C[2 * p + 1], ah, bh[2], bh[3]);
            }
        }
        __syncthreads();
        if (k + 2 < NCHUNKS) {
            load_stage(sb + (uint32_t)(k & 1) * STAGE_BYTES, rowBase, n0, (k + 2) * KC, tid);
            CP_COMMIT();
        }
    }

    // ---- epilogue: tanh * proj, reduce over columns ----
    float acc[2] = {0.f, 0.f};
#pragma unroll
    for (int in_ = 0; in_ < 8; ++in_) {
        const int col = wn * 64 + in_ * 8 + 2 * tg;
        const float p0 = projs[col];
        const float p1 = projs[col + 1];
        acc[0] += tanhf(C[in_][0]) * p0 + tanhf(C[in_][1]) * p1;
        acc[1] += tanhf(C[in_][2]) * p0 + tanhf(C[in_][3]) * p1;
    }
#pragma unroll
    for (int i = 0; i < 2; ++i) {
        acc[i] += __shfl_xor_sync(0xffffffff, acc[i], 1);
        acc[i] += __shfl_xor_sync(0xffffffff, acc[i], 2);
    }
    if (tg == 0) {
#pragma unroll
        for (int i = 0; i < 2; ++i) {
            const int row = wm * 16 + i * 8 + g;
            red[wn * 64 + row] = acc[i];
        }
    }
    __syncthreads();
    if (tid < 64) {
        float s = red[tid] + red[64 + tid] + red[128 + tid] + red[192 + tid];
        g_part[nt * M_TOTAL + rowBase + tid] = s;
    }
}

// ---------------- output: sliding-window softmax + weighted sum ----------------
// Each block: one batch b, 16 consecutive timesteps. 3-row window kept in regs.
#define CHUNK_T 16
__global__ __launch_bounds__(256)
void output_kernel(const float* __restrict__ X, float* __restrict__ out)
{
    __shared__ float s_sc[CHUNK_T + 2];          // scores for t' = t0-3 .. t0+CHUNK_T-2
    __shared__ float s_w[CHUNK_T][3];            // softmax weights per output t

    const int blk = blockIdx.x;
    const int b   = blk & (B_DIM - 1);
    const int t0  = (blk >> 4) * CHUNK_T;
    const int tid = threadIdx.x;

    if (tid < CHUNK_T + 2) {
        const int tp = t0 - 3 + tid;
        float v = 0.0f;
        if (tp >= 0) {
            const int r = tp * B_DIM + b;
            v = g_part[r] + g_part[M_TOTAL + r]
              + g_part[2 * M_TOTAL + r] + g_part[3 * M_TOTAL + r];
        }
        s_sc[tid] = v;
    }
    __syncthreads();
    if (tid < CHUNK_T) {
        const int t = t0 + tid;
        if (t >= W_ATT) {
            const float s0 = s_sc[tid], s1 = s_sc[tid + 1], s2 = s_sc[tid + 2];
            const float m  = fmaxf(s0, fmaxf(s1, s2));
            const float e0 = expf(s0 - m);
            const float e1 = expf(s1 - m);
            const float e2 = expf(s2 - m);
            const float inv = 1.0f / (e0 + e1 + e2);
            s_w[tid][0] = e0 * inv;
            s_w[tid][1] = e1 * inv;
            s_w[tid][2] = e2 * inv;
        }
    }
    __syncthreads();

    const float4* Xi = (const float4*)X;
    float4* O = (float4*)out;

    float4 p3, p2, p1;
    if (t0 >= W_ATT) {
        p3 = Xi[(size_t)((t0 - 3) * B_DIM + b) * 256 + tid];
        p2 = Xi[(size_t)((t0 - 2) * B_DIM + b) * 256 + tid];
        p1 = Xi[(size_t)((t0 - 1) * B_DIM + b) * 256 + tid];
    }

#pragma unroll
    for (int j = 0; j < CHUNK_T; ++j) {
        const int t = t0 + j;
        const size_t ridx = (size_t)(t * B_DIM + b) * 256 + tid;
        const float4 cur = Xi[ridx];
        float4 o;
        if (t < W_ATT) {
            o = cur;
        } else {
            const float a0 = s_w[j][0], a1 = s_w[j][1], a2 = s_w[j][2];
            o.x = a0 * p3.x + a1 * p2.x + a2 * p1.x;
            o.y = a0 * p3.y + a1 * p2.y + a2 * p1.y;
            o.z = a0 * p3.z + a1 * p2.z + a2 * p1.z;
            o.w = a0 * p3.w + a1 * p2.w + a2 * p1.w;
        }
        O[ridx] = o;
        p3 = p2; p2 = p1; p1 = cur;
    }
}

// ---------------- launch ----------------
extern "C" void kernel_launch(void* const* d_in, const int* in_sizes, int n_in,
                              void* d_out, int out_size)
{
    const float* X    = (const float*)d_in[0];
    const float* Wm   = (const float*)d_in[1];
    const float* proj = (const float*)d_in[2];
    float* out        = (float*)d_out;

    cudaFuncSetAttribute(gemm_scores_kernel,
                         cudaFuncAttributeMaxDynamicSharedMemorySize,
                         SMEM_TOTAL_GEMM);

    convert_x_kernel<<<M_TOTAL * H_DIM / 4 / 256, 256>>>(X);
    convert_w_kernel<<<dim3(H_DIM / 32, H_DIM / 32), dim3(32, 32)>>>(Wm);
    gemm_scores_kernel<<<MTILES * NTILES, GEMM_THREADS, SMEM_TOTAL_GEMM>>>(proj);
    output_kernel<<<(T_DIM / CHUNK_T) * B_DIM, 256>>>(X, out);
}

// round 16
// speedup vs baseline: 1.1543x; 1.1543x over previous
#include <cuda_runtime.h>
#include <cuda_fp16.h>
#include <cstdint>

// ---------------- problem constants ----------------
#define T_DIM   2048
#define B_DIM   16
#define H_DIM   1024
#define M_TOTAL (T_DIM * B_DIM)     // 32768 rows
#define W_ATT   3

// ---------------- GEMM tiling ----------------
#define TILE_M   128
#define TILE_N   256
#define KC       64                  // k elems per chunk
#define NCHUNKS  (H_DIM / KC)        // 16
#define NTILES   (H_DIM / TILE_N)    // 4
#define MTILES   (M_TOTAL / TILE_M)  // 256
#define GEMM_THREADS 512
#define NSTAGES  3

// SMEM row stride: 64 fp16 = 128B data, padded to 144B (conflict-free ldmatrix)
#define ROWB     144
#define A_BYTES  (TILE_M * ROWB)     // 18432
#define B_BYTES  (TILE_N * ROWB)     // 36864
#define A_OFF    0
#define B_OFF    A_BYTES
#define STAGE_BYTES (A_BYTES + B_BYTES)       // 55296
#define PROJ_OFF (NSTAGES * STAGE_BYTES)      // 165888 (256 floats)
#define RED_OFF  (PROJ_OFF + 1024)            // 166912 (512 floats)
#define SMEM_TOTAL_GEMM (RED_OFF + 2048)      // 168960

// ---------------- global scratch ----------------
__device__ __half g_xh[(size_t)M_TOTAL * H_DIM];
__device__ __half g_whT[(size_t)H_DIM * H_DIM];   // [n][k]
__device__ float g_part[NTILES * M_TOTAL];

// ---------------- helpers ----------------
__device__ __forceinline__ uint32_t smem_u32(const void* p) {
    uint32_t a;
    asm("{ .reg .u64 t; cvta.to.shared.u64 t, %1; cvt.u32.u64 %0, t; }" : "=r"(a) : "l"(p));
    return a;
}

__device__ __forceinline__ void cp16(uint32_t dst, const void* src) {
    asm volatile("cp.async.cg.shared.global [%0], [%1], 16;\n"
                 :: "r"(dst), "l"(__cvta_generic_to_global(src)) : "memory");
}
#define CP_COMMIT() asm volatile("cp.async.commit_group;" ::: "memory")
#define CP_WAIT0()  asm volatile("cp.async.wait_group 0;"  ::: "memory")
#define CP_WAIT1()  asm volatile("cp.async.wait_group 1;"  ::: "memory")

__device__ __forceinline__ void ldsm_x4(uint32_t* r, uint32_t addr) {
    asm volatile("ldmatrix.sync.aligned.m8n8.x4.shared.b16 {%0,%1,%2,%3}, [%4];"
                 : "=r"(r[0]), "=r"(r[1]), "=r"(r[2]), "=r"(r[3]) : "r"(addr));
}

#define MMA_F16(c, a, b0v, b1v)                                               \
    asm volatile(                                                             \
        "mma.sync.aligned.m16n8k16.row.col.f32.f16.f16.f32 "                  \
        "{%0,%1,%2,%3}, {%4,%5,%6,%7}, {%8,%9}, {%0,%1,%2,%3};\n"             \
        : "+f"((c)[0]), "+f"((c)[1]), "+f"((c)[2]), "+f"((c)[3])              \
        : "r"((a)[0]), "r"((a)[1]), "r"((a)[2]), "r"((a)[3]),                 \
          "r"(b0v), "r"(b1v))

// ---------------- convert kernels ----------------
__global__ __launch_bounds__(256)
void convert_x_kernel(const float* __restrict__ X)
{
    size_t i = (size_t)blockIdx.x * 256 + threadIdx.x;    // float4 index
    float4 v = ((const float4*)X)[i];
    __half2 h0 = __float22half2_rn(make_float2(v.x, v.y));
    __half2 h1 = __float22half2_rn(make_float2(v.z, v.w));
    uint2 u;
    u.x = *(uint32_t*)&h0; u.y = *(uint32_t*)&h1;
    ((uint2*)g_xh)[i] = u;
}

__global__ __launch_bounds__(1024)
void convert_w_kernel(const float* __restrict__ W)
{
    __shared__ float t[32][33];
    int x = blockIdx.x * 32 + threadIdx.x;   // n
    int y = blockIdx.y * 32 + threadIdx.y;   // k
    t[threadIdx.y][threadIdx.x] = W[(size_t)y * H_DIM + x];
    __syncthreads();
    int n  = blockIdx.x * 32 + threadIdx.y;
    int kk = blockIdx.y * 32 + threadIdx.x;
    g_whT[(size_t)n * H_DIM + kk] = __float2half_rn(t[threadIdx.x][threadIdx.y]);
}

// ---------------- GEMM + fused tanh/proj epilogue ----------------
__device__ __forceinline__ void load_stage(uint32_t sbStage, int rowBase, int n0,
                                           int k0, int tid)
{
    // A: 128 rows x 8 x 16B
#pragma unroll
    for (int i = 0; i < 2; ++i) {
        int c = tid + i * 512;
        int row = c >> 3, q = c & 7;
        size_t off = (size_t)(rowBase + row) * H_DIM + k0 + q * 8;
        cp16(sbStage + A_OFF + row * ROWB + q * 16, g_xh + off);
    }
    // B: 256 rows x 8 x 16B
#pragma unroll
    for (int i = 0; i < 4; ++i) {
        int c = tid + i * 512;
        int row = c >> 3, q = c & 7;
        size_t off = (size_t)(n0 + row) * H_DIM + k0 + q * 8;
        cp16(sbStage + B_OFF + row * ROWB + q * 16, g_whT + off);
    }
}

__global__ __launch_bounds__(GEMM_THREADS, 1)
void gemm_scores_kernel(const float* __restrict__ proj)
{
    extern __shared__ __align__(16) char smem_raw[];
    const uint32_t sb = smem_u32(smem_raw);
    const int tid  = threadIdx.x;
    const int lane = tid & 31;
    const int wid  = tid >> 5;
    const int g    = lane >> 2;
    const int tg   = lane & 3;
    const int wm   = wid & 3;     // warp M (0..3): rows wm*32..+32
    const int wn   = wid >> 2;    // warp N (0..3): cols wn*64..+64

    const int mt = blockIdx.x >> 2;
    const int nt = blockIdx.x & 3;
    const int rowBase = mt * TILE_M;
    const int n0 = nt * TILE_N;

    float* projs = (float*)(smem_raw + PROJ_OFF);
    float* red   = (float*)(smem_raw + RED_OFF);
    if (tid < 256) projs[tid] = proj[n0 + tid];

    float C[2][8][4];
#pragma unroll
    for (int im = 0; im < 2; ++im)
#pragma unroll
        for (int in_ = 0; in_ < 8; ++in_)
#pragma unroll
            for (int e = 0; e < 4; ++e) C[im][in_][e] = 0.0f;

    // per-lane ldmatrix base addresses (within a stage)
    const uint32_t aBaseRel = (uint32_t)(A_OFF +
        (wm * 32 + (lane & 15)) * ROWB + (lane >> 4) * 16);
    const uint32_t bBaseRel = (uint32_t)(B_OFF +
        (wn * 64 + (lane & 7) + ((lane >> 4) & 1) * 8) * ROWB + ((lane >> 3) & 1) * 16);

    // prologue: stages 0,1
    load_stage(sb, rowBase, n0, 0, tid);
    CP_COMMIT();
    load_stage(sb + STAGE_BYTES, rowBase, n0, KC, tid);
    CP_COMMIT();

#pragma unroll 1
    for (int k = 0; k < NCHUNKS; ++k) {
        if (k < NCHUNKS - 1) { CP_WAIT1(); } else { CP_WAIT0(); }
        __syncthreads();

        // issue next-next stage into the ring slot freed at iter k-1
        if (k + 2 < NCHUNKS) {
            load_stage(sb + (uint32_t)((k + 2) % NSTAGES) * STAGE_BYTES,
                       rowBase, n0, (k + 2) * KC, tid);
            CP_COMMIT();
        }

        const uint32_t sBase = sb + (uint32_t)(k % NSTAGES) * STAGE_BYTES;
        const uint32_t aB = sBase + aBaseRel;
        const uint32_t bB = sBase + bBaseRel;

        // register-double-buffered fragment pipeline over (ks, p)
        uint32_t ah[2][4], ahn[2][4], bhc[4], bhn[4];
        ldsm_x4(ah[0], aB);
        ldsm_x4(ah[1], aB + 16 * ROWB);
        ldsm_x4(bhc, bB);

#pragma unroll
        for (int idx = 0; idx < 16; ++idx) {
            const int p = idx & 3;
            if (idx < 15) {
                const int nks = (idx + 1) >> 2;
                const int np  = (idx + 1) & 3;
                ldsm_x4(bhn, bB + np * (16 * ROWB) + nks * 32);
                if (np == 0) {
                    ldsm_x4(ahn[0], aB + nks * 32);
                    ldsm_x4(ahn[1], aB + 16 * ROWB + nks * 32);
                }
            }
            MMA_F16(C[0][2 * p],     ah[0], bhc[0], bhc[1]);
            MMA_F16(C[0][2 * p + 1], ah[0], bhc[2], bhc[3]);
            MMA_F16(C[1][2 * p],     ah[1], bhc[0], bhc[1]);
            MMA_F16(C[1][2 * p + 1], ah[1], bhc[2], bhc[3]);
#pragma unroll
            for (int j = 0; j < 4; ++j) bhc[j] = bhn[j];
            if (p == 3) {
#pragma unroll
                for (int j = 0; j < 4; ++j) { ah[0][j] = ahn[0][j]; ah[1][j] = ahn[1][j]; }
            }
        }
    }

    // ---- epilogue: tanh * proj, reduce over columns ----
    float acc[4] = {0.f, 0.f, 0.f, 0.f};
#pragma unroll
    for (int im = 0; im < 2; ++im) {
#pragma unroll
        for (int in_ = 0; in_ < 8; ++in_) {
            const int col = wn * 64 + in_ * 8 + 2 * tg;
            const float p0 = projs[col];
            const float p1 = projs[col + 1];
            acc[im * 2 + 0] += tanhf(C[im][in_][0]) * p0 + tanhf(C[im][in_][1]) * p1;
            acc[im * 2 + 1] += tanhf(C[im][in_][2]) * p0 + tanhf(C[im][in_][3]) * p1;
        }
    }
#pragma unroll
    for (int i = 0; i < 4; ++i) {
        acc[i] += __shfl_xor_sync(0xffffffff, acc[i], 1);
        acc[i] += __shfl_xor_sync(0xffffffff, acc[i], 2);
    }
    if (tg == 0) {
#pragma unroll
        for (int i = 0; i < 4; ++i) {
            const int im = i >> 1, half = i & 1;
            const int row = wm * 32 + im * 16 + half * 8 + g;
            red[wn * 128 + row] = acc[i];
        }
    }
    __syncthreads();
    if (tid < 128) {
        float s = red[tid] + red[128 + tid] + red[256 + tid] + red[384 + tid];
        g_part[nt * M_TOTAL + rowBase + tid] = s;
    }
}

// ---------------- output: sliding-window softmax + weighted sum ----------------
// Each block: one batch b, 8 consecutive timesteps. 3-row window kept in regs.
#define CHUNK_T 8
__global__ __launch_bounds__(256)
void output_kernel(const float* __restrict__ X, float* __restrict__ out)
{
    __shared__ float s_sc[CHUNK_T + 2];          // scores for t' = t0-3 .. t0+6
    __shared__ float s_w[CHUNK_T][3];            // softmax weights per output t

    const int blk = blockIdx.x;
    const int b   = blk & (B_DIM - 1);
    const int t0  = (blk >> 4) * CHUNK_T;
    const int tid = threadIdx.x;

    if (tid < CHUNK_T + 2) {
        const int tp = t0 - 3 + tid;
        float v = 0.0f;
        if (tp >= 0) {
            const int r = tp * B_DIM + b;
            v = g_part[r] + g_part[M_TOTAL + r]
              + g_part[2 * M_TOTAL + r] + g_part[3 * M_TOTAL + r];
        }
        s_sc[tid] = v;
    }
    __syncthreads();
    if (tid < CHUNK_T) {
        const int t = t0 + tid;
        if (t >= W_ATT) {
            const float s0 = s_sc[tid], s1 = s_sc[tid + 1], s2 = s_sc[tid + 2];
            const float m  = fmaxf(s0, fmaxf(s1, s2));
            const float e0 = expf(s0 - m);
            const float e1 = expf(s1 - m);
            const float e2 = expf(s2 - m);
            const float inv = 1.0f / (e0 + e1 + e2);
            s_w[tid][0] = e0 * inv;
            s_w[tid][1] = e1 * inv;
            s_w[tid][2] = e2 * inv;
        }
    }
    __syncthreads();

    const float4* Xi = (const float4*)X;
    float4* O = (float4*)out;

    float4 p3, p2, p1;
    if (t0 >= W_ATT) {
        p3 = Xi[(size_t)((t0 - 3) * B_DIM + b) * 256 + tid];
        p2 = Xi[(size_t)((t0 - 2) * B_DIM + b) * 256 + tid];
        p1 = Xi[(size_t)((t0 - 1) * B_DIM + b) * 256 + tid];
    }

#pragma unroll
    for (int j = 0; j < CHUNK_T; ++j) {
        const int t = t0 + j;
        const size_t ridx = (size_t)(t * B_DIM + b) * 256 + tid;
        const float4 cur = Xi[ridx];
        float4 o;
        if (t < W_ATT) {
            o = cur;
        } else {
            const float a0 = s_w[j][0], a1 = s_w[j][1], a2 = s_w[j][2];
            o.x = a0 * p3.x + a1 * p2.x + a2 * p1.x;
            o.y = a0 * p3.y + a1 * p2.y + a2 * p1.y;
            o.z = a0 * p3.z + a1 * p2.z + a2 * p1.z;
            o.w = a0 * p3.w + a1 * p2.w + a2 * p1.w;
        }
        O[ridx] = o;
        p3 = p2; p2 = p1; p1 = cur;
    }
}

// ---------------- launch ----------------
extern "C" void kernel_launch(void* const* d_in, const int* in_sizes, int n_in,
                              void* d_out, int out_size)
{
    const float* X    = (const float*)d_in[0];
    const float* Wm   = (const float*)d_in[1];
    const float* proj = (const float*)d_in[2];
    float* out        = (float*)d_out;

    cudaFuncSetAttribute(gemm_scores_kernel,
                         cudaFuncAttributeMaxDynamicSharedMemorySize,
                         SMEM_TOTAL_GEMM);

    convert_x_kernel<<<M_TOTAL * H_DIM / 4 / 256, 256>>>(X);
    convert_w_kernel<<<dim3(H_DIM / 32, H_DIM / 32), dim3(32, 32)>>>(Wm);
    gemm_scores_kernel<<<MTILES * NTILES, GEMM_THREADS, SMEM_TOTAL_GEMM>>>(proj);
    output_kernel<<<(T_DIM / CHUNK_T) * B_DIM, 256>>>(X, out);
}